// round 4
// baseline (speedup 1.0000x reference)
#include <cuda_runtime.h>
#include <cuda_fp16.h>
#include <cstdint>
#include <math.h>

constexpr int T_TOK = 4096;
constexpr int HID   = 2048;
constexpr int INTER = 5120;
constexpr int NEXP  = 8;
constexpr int ROWS_MAX = 9216;

// ---------- device scratch ----------
__device__ int   g_cnt[NEXP];
__device__ int   g_cursor[NEXP];
__device__ int   g_off[NEXP];
__device__ int   g_region[NEXP];
__device__ int   g_padded_total;
__device__ int   g_tok_e[T_TOK * 2];
__device__ float g_tok_w[T_TOK * 2];
__device__ int   g_tok_rows[T_TOK * 2];
__device__ int   g_row_token[ROWS_MAX];
__device__ __half g_Xg[(size_t)ROWS_MAX * HID];
__device__ __half g_P1[(size_t)ROWS_MAX * INTER];
__device__ __half g_G [(size_t)ROWS_MAX * INTER];
__device__ float  g_Y [(size_t)ROWS_MAX * HID];
__device__ __half g_w1t[(size_t)NEXP * INTER * HID];
__device__ __half g_w3t[(size_t)NEXP * INTER * HID];
__device__ __half g_w2t[(size_t)NEXP * HID * INTER];

// ---------- helpers ----------
__device__ __forceinline__ uint32_t smem_u32(const void* p) {
    uint32_t a;
    asm("{ .reg .u64 t; cvta.to.shared.u64 t, %1; cvt.u32.u64 %0, t; }" : "=r"(a) : "l"(p));
    return a;
}
__device__ __forceinline__ void cp16(uint32_t dst, const void* src) {
    asm volatile("cp.async.cg.shared.global [%0], [%1], 16;" :: "r"(dst), "l"(src));
}
#define CP_COMMIT() asm volatile("cp.async.commit_group;" ::: "memory")
#define CP_WAIT(n)  asm volatile("cp.async.wait_group %0;" :: "n"(n) : "memory")

__device__ __forceinline__ void ldm_x4(uint32_t* r, uint32_t a) {
    asm volatile("ldmatrix.sync.aligned.m8n8.x4.shared.b16 {%0,%1,%2,%3}, [%4];"
        : "=r"(r[0]), "=r"(r[1]), "=r"(r[2]), "=r"(r[3]) : "r"(a));
}
__device__ __forceinline__ void ldm_x2(uint32_t* r, uint32_t a) {
    asm volatile("ldmatrix.sync.aligned.m8n8.x2.shared.b16 {%0,%1}, [%2];"
        : "=r"(r[0]), "=r"(r[1]) : "r"(a));
}
__device__ __forceinline__ void mma16816(float* d, const uint32_t* a, const uint32_t* b) {
    asm volatile("mma.sync.aligned.m16n8k16.row.col.f32.f16.f16.f32 "
        "{%0,%1,%2,%3}, {%4,%5,%6,%7}, {%8,%9}, {%0,%1,%2,%3};"
        : "+f"(d[0]), "+f"(d[1]), "+f"(d[2]), "+f"(d[3])
        : "r"(a[0]), "r"(a[1]), "r"(a[2]), "r"(a[3]), "r"(b[0]), "r"(b[1]));
}
__device__ __forceinline__ float silu(float x) { return x / (1.f + expf(-x)); }

// ---------- small kernels ----------
__global__ void k_zero() {
    int t = threadIdx.x;
    if (t < NEXP) { g_cnt[t] = 0; g_cursor[t] = 0; }
}

__global__ void k_router(const float* __restrict__ hs, const float* __restrict__ gate,
                         float* __restrict__ out) {
    int warp = (blockIdx.x * blockDim.x + threadIdx.x) >> 5;
    int lane = threadIdx.x & 31;
    if (warp >= T_TOK) return;
    const float* x = hs + (size_t)warp * HID;
    float acc[NEXP];
#pragma unroll
    for (int e = 0; e < NEXP; e++) acc[e] = 0.f;
    for (int h = lane; h < HID; h += 32) {
        float xv = x[h];
        const float4* g4 = (const float4*)(gate + (size_t)h * NEXP);
        float4 a = g4[0], b = g4[1];
        acc[0] += xv * a.x; acc[1] += xv * a.y; acc[2] += xv * a.z; acc[3] += xv * a.w;
        acc[4] += xv * b.x; acc[5] += xv * b.y; acc[6] += xv * b.z; acc[7] += xv * b.w;
    }
#pragma unroll
    for (int e = 0; e < NEXP; e++)
#pragma unroll
        for (int o = 16; o; o >>= 1) acc[e] += __shfl_xor_sync(0xffffffffu, acc[e], o);
    if (lane == 0) {
        float* lo = out + (size_t)T_TOK * HID + (size_t)warp * NEXP;
#pragma unroll
        for (int e = 0; e < NEXP; e++) lo[e] = acc[e];
        int e0 = 0; float l0 = acc[0];
#pragma unroll
        for (int e = 1; e < NEXP; e++) if (acc[e] > l0) { l0 = acc[e]; e0 = e; }
        int e1 = -1; float l1 = -1e30f;
#pragma unroll
        for (int e = 0; e < NEXP; e++) if (e != e0 && acc[e] > l1) { l1 = acc[e]; e1 = e; }
        float p1 = expf(l1 - l0);
        float s = 1.f + p1;
        g_tok_e[warp * 2] = e0;      g_tok_e[warp * 2 + 1] = e1;
        g_tok_w[warp * 2] = 1.f / s; g_tok_w[warp * 2 + 1] = p1 / s;
        atomicAdd(&g_cnt[e0], 1);
        atomicAdd(&g_cnt[e1], 1);
    }
}

__global__ void k_scan() {
    int off = 0;
    for (int e = 0; e < NEXP; e++) {
        g_off[e] = off;
        int reg = ((g_cnt[e] + 127) / 128) * 128;
        g_region[e] = reg;
        off += reg;
    }
    g_padded_total = off;
}

__global__ void k_assign() {
    int t = blockIdx.x * blockDim.x + threadIdx.x;
    if (t >= T_TOK) return;
#pragma unroll
    for (int k = 0; k < 2; k++) {
        int e = g_tok_e[t * 2 + k];
        int pos = atomicAdd(&g_cursor[e], 1);
        int row = g_off[e] + pos;
        g_row_token[row] = t;
        g_tok_rows[t * 2 + k] = row;
    }
}

__global__ void k_gather(const float* __restrict__ hs) {
    int r = blockIdx.x;
    if (r >= g_padded_total) {
        // still zero rows beyond padded_total up to ROWS_MAX (cheap safety)
        uint32_t* d = (uint32_t*)(g_Xg + (size_t)r * HID);
        for (int i = threadIdx.x; i < HID / 2; i += blockDim.x) d[i] = 0u;
        return;
    }
    int e = 0;
#pragma unroll
    for (int i = 0; i < NEXP; i++)
        if (r >= g_off[i] && r < g_off[i] + g_region[i]) e = i;
    int local = r - g_off[e];
    __half* dst = g_Xg + (size_t)r * HID;
    if (local < g_cnt[e]) {
        int t = g_row_token[r];
        const float4* src = (const float4*)(hs + (size_t)t * HID);
        __half2* d2 = (__half2*)dst;
        for (int i = threadIdx.x; i < HID / 4; i += blockDim.x) {
            float4 v = src[i];
            d2[2 * i]     = __floats2half2_rn(v.x, v.y);
            d2[2 * i + 1] = __floats2half2_rn(v.z, v.w);
        }
    } else {
        uint32_t* d = (uint32_t*)dst;
        for (int i = threadIdx.x; i < HID / 2; i += blockDim.x) d[i] = 0u;
    }
}

// f32 in[E][R][C] -> f16 out[E][C][R]
__global__ void k_transpose(const float* __restrict__ in, __half* __restrict__ out,
                            int R, int C) {
    __shared__ float tile[32][33];
    size_t eoff = (size_t)blockIdx.z * R * C;
    int x = blockIdx.x * 32 + threadIdx.x;
    int y0 = blockIdx.y * 32;
#pragma unroll
    for (int j = threadIdx.y; j < 32; j += 8)
        tile[j][threadIdx.x] = in[eoff + (size_t)(y0 + j) * C + x];
    __syncthreads();
    int ox = y0 + threadIdx.x;
    int oy0 = blockIdx.x * 32;
#pragma unroll
    for (int j = threadIdx.y; j < 32; j += 8)
        out[eoff + (size_t)(oy0 + j) * R + ox] = __float2half(tile[threadIdx.x][j]);
}

// ---------- HMMA GEMM ----------
// CTA 256 threads, tile M=128 N=128, K-chunk 32, double-buffered cp.async.
// Warp grid 2(M) x 4(N); warp tile 64x32 = 4x4 m16n8k16 atoms.
// smem rows padded: 32 halves data + 8 pad = 40 halves (80 B) per row.
constexpr int SROW = 40;               // halves per smem row
constexpr int STAGE_B = 128 * SROW * 2; // bytes per tile per stage (10240)

// MODE 0: out g_P1 (fp16 raw).  MODE 1: out g_G = silu(P1)*acc (fp16).
// MODE 2: out g_Y (fp32).
template <int MODE>
__global__ void __launch_bounds__(256) k_gemm(const __half* __restrict__ A,
                                              const __half* __restrict__ Bt,
                                              int K, int Ntot) {
    __shared__ __half sA[2 * 128 * SROW];
    __shared__ __half sB[2 * 128 * SROW];

    int m0 = blockIdx.x * 128;
    if (m0 >= g_padded_total) return;
    int e = 0;
#pragma unroll
    for (int i = 0; i < NEXP; i++)
        if (m0 >= g_off[i] && m0 < g_off[i] + g_region[i]) e = i;
    int n0 = blockIdx.y * 128;

    const __half* Ag = A + (size_t)m0 * K;
    const __half* Bg = Bt + ((size_t)e * Ntot + n0) * K;

    int tid = threadIdx.x;
    int wid = tid >> 5, lane = tid & 31;
    int wm = wid >> 2, wn = wid & 3;

    uint32_t uA = smem_u32(sA);
    uint32_t uB = smem_u32(sB);

    // cp.async indices (each thread: 2 A vecs + 2 B vecs per chunk)
    int r0 = tid >> 2, q0 = tid & 3;            // idx = tid
    int r1 = (tid + 256) >> 2, q1 = tid & 3;    // idx = tid + 256

    float d[4][4][4];
#pragma unroll
    for (int i = 0; i < 4; i++)
#pragma unroll
        for (int j = 0; j < 4; j++)
#pragma unroll
            for (int k = 0; k < 4; k++) d[i][j][k] = 0.f;

    const int NC = K / 32;

    auto load_chunk = [&](int st, int c) {
        int kg = c * 32;
        uint32_t aoff = (uint32_t)st * STAGE_B;
        cp16(uA + aoff + (uint32_t)(r0 * SROW + q0 * 8) * 2, Ag + (size_t)r0 * K + kg + q0 * 8);
        cp16(uA + aoff + (uint32_t)(r1 * SROW + q1 * 8) * 2, Ag + (size_t)r1 * K + kg + q1 * 8);
        cp16(uB + aoff + (uint32_t)(r0 * SROW + q0 * 8) * 2, Bg + (size_t)r0 * K + kg + q0 * 8);
        cp16(uB + aoff + (uint32_t)(r1 * SROW + q1 * 8) * 2, Bg + (size_t)r1 * K + kg + q1 * 8);
    };

    load_chunk(0, 0);
    CP_COMMIT();

    for (int c = 0; c < NC; c++) {
        int st = c & 1;
        if (c + 1 < NC) {
            load_chunk(st ^ 1, c + 1);
            CP_COMMIT();
            CP_WAIT(1);
        } else {
            CP_WAIT(0);
        }
        __syncthreads();

        uint32_t base = (uint32_t)st * STAGE_B;
#pragma unroll
        for (int ks = 0; ks < 2; ks++) {
            uint32_t a[4][4], b[4][2];
#pragma unroll
            for (int am = 0; am < 4; am++) {
                int row = wm * 64 + am * 16 + (lane & 15);
                int col = ks * 16 + (lane >> 4) * 8;
                ldm_x4(a[am], uA + base + (uint32_t)(row * SROW + col) * 2);
            }
#pragma unroll
            for (int bn = 0; bn < 4; bn++) {
                int rowB = wn * 32 + bn * 8 + (lane & 7);
                int col = ks * 16 + ((lane >> 3) & 1) * 8;
                ldm_x2(b[bn], uB + base + (uint32_t)(rowB * SROW + col) * 2);
            }
#pragma unroll
            for (int am = 0; am < 4; am++)
#pragma unroll
                for (int bn = 0; bn < 4; bn++)
                    mma16816(d[am][bn], a[am], b[bn]);
        }
        __syncthreads();
    }

    // epilogue
    int rbase = m0 + wm * 64 + (lane >> 2);
    int cbase = n0 + wn * 32 + (lane & 3) * 2;
#pragma unroll
    for (int am = 0; am < 4; am++) {
#pragma unroll
        for (int bn = 0; bn < 4; bn++) {
            int r = rbase + am * 16;
            int cc = cbase + bn * 8;
            float* dd = d[am][bn];
            if (MODE == 0) {
                *(__half2*)(g_P1 + (size_t)r * Ntot + cc)       = __floats2half2_rn(dd[0], dd[1]);
                *(__half2*)(g_P1 + (size_t)(r + 8) * Ntot + cc) = __floats2half2_rn(dd[2], dd[3]);
            } else if (MODE == 1) {
                __half2 p1a = *(const __half2*)(g_P1 + (size_t)r * Ntot + cc);
                __half2 p1b = *(const __half2*)(g_P1 + (size_t)(r + 8) * Ntot + cc);
                float g0 = silu(__half2float(p1a.x)) * dd[0];
                float g1 = silu(__half2float(p1a.y)) * dd[1];
                float g2 = silu(__half2float(p1b.x)) * dd[2];
                float g3 = silu(__half2float(p1b.y)) * dd[3];
                *(__half2*)(g_G + (size_t)r * Ntot + cc)       = __floats2half2_rn(g0, g1);
                *(__half2*)(g_G + (size_t)(r + 8) * Ntot + cc) = __floats2half2_rn(g2, g3);
            } else {
                *(float2*)(g_Y + (size_t)r * Ntot + cc)       = make_float2(dd[0], dd[1]);
                *(float2*)(g_Y + (size_t)(r + 8) * Ntot + cc) = make_float2(dd[2], dd[3]);
            }
        }
    }
}

__global__ void k_combine(float* __restrict__ out) {
    int t = blockIdx.x;
    int r0 = g_tok_rows[t * 2], r1 = g_tok_rows[t * 2 + 1];
    float w0 = g_tok_w[t * 2], w1 = g_tok_w[t * 2 + 1];
    const float4* y0 = (const float4*)(g_Y + (size_t)r0 * HID);
    const float4* y1 = (const float4*)(g_Y + (size_t)r1 * HID);
    float4* o = (float4*)(out + (size_t)t * HID);
    for (int i = threadIdx.x; i < HID / 4; i += blockDim.x) {
        float4 a = y0[i], b = y1[i];
        float4 v;
        v.x = w0 * a.x + w1 * b.x;
        v.y = w0 * a.y + w1 * b.y;
        v.z = w0 * a.z + w1 * b.z;
        v.w = w0 * a.w + w1 * b.w;
        o[i] = v;
    }
}

// ---------- launch ----------
extern "C" void kernel_launch(void* const* d_in, const int* in_sizes, int n_in,
                              void* d_out, int out_size) {
    const float* hs   = (const float*)d_in[0];
    const float* gate = (const float*)d_in[1];
    const float* w1   = (const float*)d_in[2];
    const float* w3   = (const float*)d_in[3];
    const float* w2   = (const float*)d_in[4];
    float* out = (float*)d_out;

    __half *w1t, *w3t, *w2t, *Xg, *G;
    cudaGetSymbolAddress((void**)&w1t, g_w1t);
    cudaGetSymbolAddress((void**)&w3t, g_w3t);
    cudaGetSymbolAddress((void**)&w2t, g_w2t);
    cudaGetSymbolAddress((void**)&Xg,  g_Xg);
    cudaGetSymbolAddress((void**)&G,   g_G);

    k_zero<<<1, 32>>>();
    k_router<<<T_TOK / 8, 256>>>(hs, gate, out);
    k_scan<<<1, 1>>>();
    k_assign<<<T_TOK / 256, 256>>>();
    k_gather<<<ROWS_MAX, 128>>>(hs);

    dim3 tb(32, 8);
    k_transpose<<<dim3(INTER / 32, HID / 32, NEXP), tb>>>(w1, w1t, HID, INTER);
    k_transpose<<<dim3(INTER / 32, HID / 32, NEXP), tb>>>(w3, w3t, HID, INTER);
    k_transpose<<<dim3(HID / 32, INTER / 32, NEXP), tb>>>(w2, w2t, INTER, HID);

    k_gemm<0><<<dim3(ROWS_MAX / 128, INTER / 128), 256>>>(Xg, w1t, HID, INTER);
    k_gemm<1><<<dim3(ROWS_MAX / 128, INTER / 128), 256>>>(Xg, w3t, HID, INTER);
    k_gemm<2><<<dim3(ROWS_MAX / 128, HID / 128), 256>>>(G, w2t, INTER, HID);

    k_combine<<<T_TOK, 256>>>(out);
}

// round 5
// speedup vs baseline: 1.4275x; 1.4275x over previous
#include <cuda_runtime.h>
#include <cuda_fp16.h>
#include <cstdint>
#include <math.h>

constexpr int T_TOK = 4096;
constexpr int HID   = 2048;
constexpr int INTER = 5120;
constexpr int NEXP  = 8;
constexpr int ROWS_MAX = 9216;

// ---------- device scratch ----------
__device__ int   g_cnt[NEXP];
__device__ int   g_cursor[NEXP];
__device__ int   g_off[NEXP];
__device__ int   g_region[NEXP];
__device__ int   g_padded_total;
__device__ int   g_tok_e[T_TOK * 2];
__device__ float g_tok_w[T_TOK * 2];
__device__ int   g_tok_rows[T_TOK * 2];
__device__ int   g_row_token[ROWS_MAX];
__device__ __half g_Xg[(size_t)ROWS_MAX * HID];
__device__ __half g_G [(size_t)ROWS_MAX * INTER];
__device__ float  g_Y [(size_t)ROWS_MAX * HID];
__device__ __half g_w1h[(size_t)NEXP * HID * INTER];   // fp16, native [E][K=H][N=I]
__device__ __half g_w3h[(size_t)NEXP * HID * INTER];
__device__ __half g_w2h[(size_t)NEXP * INTER * HID];   // fp16, native [E][K=I][N=H]

// ---------- helpers ----------
__device__ __forceinline__ uint32_t smem_u32(const void* p) {
    uint32_t a;
    asm("{ .reg .u64 t; cvta.to.shared.u64 t, %1; cvt.u32.u64 %0, t; }" : "=r"(a) : "l"(p));
    return a;
}
__device__ __forceinline__ void cp16(uint32_t dst, const void* src) {
    asm volatile("cp.async.cg.shared.global [%0], [%1], 16;" :: "r"(dst), "l"(src));
}
#define CP_COMMIT() asm volatile("cp.async.commit_group;" ::: "memory")
#define CP_WAIT(n)  asm volatile("cp.async.wait_group %0;" :: "n"(n) : "memory")

__device__ __forceinline__ void ldm_x4(uint32_t* r, uint32_t a) {
    asm volatile("ldmatrix.sync.aligned.m8n8.x4.shared.b16 {%0,%1,%2,%3}, [%4];"
        : "=r"(r[0]), "=r"(r[1]), "=r"(r[2]), "=r"(r[3]) : "r"(a));
}
__device__ __forceinline__ void ldm_x2t(uint32_t* r, uint32_t a) {
    asm volatile("ldmatrix.sync.aligned.m8n8.x2.trans.shared.b16 {%0,%1}, [%2];"
        : "=r"(r[0]), "=r"(r[1]) : "r"(a));
}
__device__ __forceinline__ void mma16816(float* d, const uint32_t* a, const uint32_t* b) {
    asm volatile("mma.sync.aligned.m16n8k16.row.col.f32.f16.f16.f32 "
        "{%0,%1,%2,%3}, {%4,%5,%6,%7}, {%8,%9}, {%0,%1,%2,%3};"
        : "+f"(d[0]), "+f"(d[1]), "+f"(d[2]), "+f"(d[3])
        : "r"(a[0]), "r"(a[1]), "r"(a[2]), "r"(a[3]), "r"(b[0]), "r"(b[1]));
}
__device__ __forceinline__ float silu(float x) { return x / (1.f + expf(-x)); }

// ---------- small kernels ----------
__global__ void k_zero() {
    int t = threadIdx.x;
    if (t < NEXP) { g_cnt[t] = 0; g_cursor[t] = 0; }
}

__global__ void k_router(const float* __restrict__ hs, const float* __restrict__ gate,
                         float* __restrict__ out) {
    int warp = (blockIdx.x * blockDim.x + threadIdx.x) >> 5;
    int lane = threadIdx.x & 31;
    if (warp >= T_TOK) return;
    const float* x = hs + (size_t)warp * HID;
    float acc[NEXP];
#pragma unroll
    for (int e = 0; e < NEXP; e++) acc[e] = 0.f;
    for (int h = lane; h < HID; h += 32) {
        float xv = x[h];
        const float4* g4 = (const float4*)(gate + (size_t)h * NEXP);
        float4 a = g4[0], b = g4[1];
        acc[0] += xv * a.x; acc[1] += xv * a.y; acc[2] += xv * a.z; acc[3] += xv * a.w;
        acc[4] += xv * b.x; acc[5] += xv * b.y; acc[6] += xv * b.z; acc[7] += xv * b.w;
    }
#pragma unroll
    for (int e = 0; e < NEXP; e++)
#pragma unroll
        for (int o = 16; o; o >>= 1) acc[e] += __shfl_xor_sync(0xffffffffu, acc[e], o);
    if (lane == 0) {
        float* lo = out + (size_t)T_TOK * HID + (size_t)warp * NEXP;
#pragma unroll
        for (int e = 0; e < NEXP; e++) lo[e] = acc[e];
        int e0 = 0; float l0 = acc[0];
#pragma unroll
        for (int e = 1; e < NEXP; e++) if (acc[e] > l0) { l0 = acc[e]; e0 = e; }
        int e1 = -1; float l1 = -1e30f;
#pragma unroll
        for (int e = 0; e < NEXP; e++) if (e != e0 && acc[e] > l1) { l1 = acc[e]; e1 = e; }
        float p1 = expf(l1 - l0);
        float s = 1.f + p1;
        g_tok_e[warp * 2] = e0;      g_tok_e[warp * 2 + 1] = e1;
        g_tok_w[warp * 2] = 1.f / s; g_tok_w[warp * 2 + 1] = p1 / s;
        atomicAdd(&g_cnt[e0], 1);
        atomicAdd(&g_cnt[e1], 1);
    }
}

__global__ void k_scan() {
    int off = 0;
    for (int e = 0; e < NEXP; e++) {
        g_off[e] = off;
        int reg = ((g_cnt[e] + 127) / 128) * 128;
        g_region[e] = reg;
        off += reg;
    }
    g_padded_total = off;
}

__global__ void k_assign() {
    int t = blockIdx.x * blockDim.x + threadIdx.x;
    if (t >= T_TOK) return;
#pragma unroll
    for (int k = 0; k < 2; k++) {
        int e = g_tok_e[t * 2 + k];
        int pos = atomicAdd(&g_cursor[e], 1);
        int row = g_off[e] + pos;
        g_row_token[row] = t;
        g_tok_rows[t * 2 + k] = row;
    }
}

__global__ void k_gather(const float* __restrict__ hs) {
    int r = blockIdx.x;
    int e = 0;
    bool valid = (r < g_padded_total);
    if (valid) {
#pragma unroll
        for (int i = 0; i < NEXP; i++)
            if (r >= g_off[i] && r < g_off[i] + g_region[i]) e = i;
    }
    __half* dst = g_Xg + (size_t)r * HID;
    if (valid && (r - g_off[e]) < g_cnt[e]) {
        int t = g_row_token[r];
        const float4* src = (const float4*)(hs + (size_t)t * HID);
        __half2* d2 = (__half2*)dst;
        for (int i = threadIdx.x; i < HID / 4; i += blockDim.x) {
            float4 v = src[i];
            d2[2 * i]     = __floats2half2_rn(v.x, v.y);
            d2[2 * i + 1] = __floats2half2_rn(v.z, v.w);
        }
    } else {
        uint32_t* d = (uint32_t*)dst;
        for (int i = threadIdx.x; i < HID / 2; i += blockDim.x) d[i] = 0u;
    }
}

// straight fp32 -> fp16 convert, fully coalesced
__global__ void k_convert(const float* __restrict__ src, __half* __restrict__ dst, int n4) {
    int i = blockIdx.x * blockDim.x + threadIdx.x;
    int stride = gridDim.x * blockDim.x;
    const float4* s4 = (const float4*)src;
    __half2* d2 = (__half2*)dst;
    for (; i < n4; i += stride) {
        float4 v = s4[i];
        d2[2 * i]     = __floats2half2_rn(v.x, v.y);
        d2[2 * i + 1] = __floats2half2_rn(v.z, v.w);
    }
}

// ---------- GEMM kernels ----------
// A smem: [m=128][k=32] fp16, row pitch 40 halves (80B)
// B smem: [k=32][n=128] fp16, row pitch 136 halves (272B) -> conflict-free ldmatrix.trans
constexpr int SROW_A  = 40;
constexpr int A_STAGE = 128 * SROW_A * 2;   // 10240 B
constexpr int SROW_B  = 136;
constexpr int B_STAGE = 32 * SROW_B * 2;    // 8704 B
constexpr int OFF_B1  = 2 * A_STAGE;        // 20480
constexpr int OFF_B3  = OFF_B1 + 2 * B_STAGE; // 37888
constexpr int SM13    = OFF_B3 + 2 * B_STAGE; // 55296
constexpr int SM2     = OFF_B1 + 2 * B_STAGE; // 37888

// Fused GEMM1: G = silu(X @ W1) * (X @ W3), W in [K][N] layout. K=HID, Ntot=INTER.
__global__ void __launch_bounds__(256, 1) k_gemm13() {
    extern __shared__ char sm[];
    int m0 = blockIdx.x * 128;
    if (m0 >= g_padded_total) return;
    int e = 0;
#pragma unroll
    for (int i = 0; i < NEXP; i++)
        if (m0 >= g_off[i] && m0 < g_off[i] + g_region[i]) e = i;
    int n0 = blockIdx.y * 128;

    const __half* Ag  = g_Xg + (size_t)m0 * HID;
    const __half* B1g = g_w1h + (size_t)e * HID * INTER + n0;
    const __half* B3g = g_w3h + (size_t)e * HID * INTER + n0;

    int tid = threadIdx.x;
    int wid = tid >> 5, lane = tid & 31;
    int wm = wid >> 2, wn = wid & 3;

    uint32_t uA  = smem_u32(sm);
    uint32_t uB1 = uA + OFF_B1;
    uint32_t uB3 = uA + OFF_B3;

    int ra0 = tid >> 2,          qa0 = tid & 3;
    int ra1 = (tid + 256) >> 2,  qa1 = tid & 3;
    int rb0 = tid >> 4,          qb0 = tid & 15;
    int rb1 = (tid + 256) >> 4,  qb1 = tid & 15;

    float d1[4][4][4], d3[4][4][4];
#pragma unroll
    for (int i = 0; i < 4; i++)
#pragma unroll
        for (int j = 0; j < 4; j++)
#pragma unroll
            for (int k = 0; k < 4; k++) { d1[i][j][k] = 0.f; d3[i][j][k] = 0.f; }

    const int NC = HID / 32;

    auto load_chunk = [&](int st, int c) {
        int kg = c * 32;
        uint32_t ao = uA + (uint32_t)st * A_STAGE;
        cp16(ao + (uint32_t)(ra0 * SROW_A + qa0 * 8) * 2, Ag + (size_t)ra0 * HID + kg + qa0 * 8);
        cp16(ao + (uint32_t)(ra1 * SROW_A + qa1 * 8) * 2, Ag + (size_t)ra1 * HID + kg + qa1 * 8);
        uint32_t b1o = uB1 + (uint32_t)st * B_STAGE;
        uint32_t b3o = uB3 + (uint32_t)st * B_STAGE;
        cp16(b1o + (uint32_t)(rb0 * SROW_B + qb0 * 8) * 2, B1g + (size_t)(kg + rb0) * INTER + qb0 * 8);
        cp16(b1o + (uint32_t)(rb1 * SROW_B + qb1 * 8) * 2, B1g + (size_t)(kg + rb1) * INTER + qb1 * 8);
        cp16(b3o + (uint32_t)(rb0 * SROW_B + qb0 * 8) * 2, B3g + (size_t)(kg + rb0) * INTER + qb0 * 8);
        cp16(b3o + (uint32_t)(rb1 * SROW_B + qb1 * 8) * 2, B3g + (size_t)(kg + rb1) * INTER + qb1 * 8);
    };

    load_chunk(0, 0);
    CP_COMMIT();

    for (int c = 0; c < NC; c++) {
        int st = c & 1;
        if (c + 1 < NC) { load_chunk(st ^ 1, c + 1); CP_COMMIT(); CP_WAIT(1); }
        else           { CP_WAIT(0); }
        __syncthreads();

        uint32_t aB  = uA  + (uint32_t)st * A_STAGE;
        uint32_t b1B = uB1 + (uint32_t)st * B_STAGE;
        uint32_t b3B = uB3 + (uint32_t)st * B_STAGE;
#pragma unroll
        for (int ks = 0; ks < 2; ks++) {
            uint32_t a[4][4];
#pragma unroll
            for (int am = 0; am < 4; am++) {
                int row = wm * 64 + am * 16 + (lane & 15);
                int col = ks * 16 + (lane >> 4) * 8;
                ldm_x4(a[am], aB + (uint32_t)(row * SROW_A + col) * 2);
            }
            int krow = ks * 16 + (lane & 15);
#pragma unroll
            for (int bn = 0; bn < 4; bn++) {
                int ncol = wn * 32 + bn * 8;
                uint32_t off = (uint32_t)(krow * SROW_B + ncol) * 2;
                uint32_t b1[2], b3[2];
                ldm_x2t(b1, b1B + off);
                ldm_x2t(b3, b3B + off);
#pragma unroll
                for (int am = 0; am < 4; am++) {
                    mma16816(d1[am][bn], a[am], b1);
                    mma16816(d3[am][bn], a[am], b3);
                }
            }
        }
        __syncthreads();
    }

    int rbase = m0 + wm * 64 + (lane >> 2);
    int cbase = n0 + wn * 32 + (lane & 3) * 2;
#pragma unroll
    for (int am = 0; am < 4; am++) {
#pragma unroll
        for (int bn = 0; bn < 4; bn++) {
            int r = rbase + am * 16;
            int cc = cbase + bn * 8;
            float* a1 = d1[am][bn];
            float* a3 = d3[am][bn];
            float g0 = silu(a1[0]) * a3[0];
            float g1 = silu(a1[1]) * a3[1];
            float g2 = silu(a1[2]) * a3[2];
            float g3 = silu(a1[3]) * a3[3];
            *(__half2*)(g_G + (size_t)r * INTER + cc)       = __floats2half2_rn(g0, g1);
            *(__half2*)(g_G + (size_t)(r + 8) * INTER + cc) = __floats2half2_rn(g2, g3);
        }
    }
}

// GEMM2: Y = G @ W2, W2 in [K=INTER][N=HID] layout, fp32 out.
__global__ void __launch_bounds__(256, 1) k_gemm2() {
    extern __shared__ char sm[];
    int m0 = blockIdx.x * 128;
    if (m0 >= g_padded_total) return;
    int e = 0;
#pragma unroll
    for (int i = 0; i < NEXP; i++)
        if (m0 >= g_off[i] && m0 < g_off[i] + g_region[i]) e = i;
    int n0 = blockIdx.y * 128;

    const __half* Ag = g_G + (size_t)m0 * INTER;
    const __half* Bg = g_w2h + (size_t)e * INTER * HID + n0;

    int tid = threadIdx.x;
    int wid = tid >> 5, lane = tid & 31;
    int wm = wid >> 2, wn = wid & 3;

    uint32_t uA = smem_u32(sm);
    uint32_t uB = uA + OFF_B1;

    int ra0 = tid >> 2,          qa0 = tid & 3;
    int ra1 = (tid + 256) >> 2,  qa1 = tid & 3;
    int rb0 = tid >> 4,          qb0 = tid & 15;
    int rb1 = (tid + 256) >> 4,  qb1 = tid & 15;

    float d[4][4][4];
#pragma unroll
    for (int i = 0; i < 4; i++)
#pragma unroll
        for (int j = 0; j < 4; j++)
#pragma unroll
            for (int k = 0; k < 4; k++) d[i][j][k] = 0.f;

    const int NC = INTER / 32;

    auto load_chunk = [&](int st, int c) {
        int kg = c * 32;
        uint32_t ao = uA + (uint32_t)st * A_STAGE;
        cp16(ao + (uint32_t)(ra0 * SROW_A + qa0 * 8) * 2, Ag + (size_t)ra0 * INTER + kg + qa0 * 8);
        cp16(ao + (uint32_t)(ra1 * SROW_A + qa1 * 8) * 2, Ag + (size_t)ra1 * INTER + kg + qa1 * 8);
        uint32_t bo = uB + (uint32_t)st * B_STAGE;
        cp16(bo + (uint32_t)(rb0 * SROW_B + qb0 * 8) * 2, Bg + (size_t)(kg + rb0) * HID + qb0 * 8);
        cp16(bo + (uint32_t)(rb1 * SROW_B + qb1 * 8) * 2, Bg + (size_t)(kg + rb1) * HID + qb1 * 8);
    };

    load_chunk(0, 0);
    CP_COMMIT();

    for (int c = 0; c < NC; c++) {
        int st = c & 1;
        if (c + 1 < NC) { load_chunk(st ^ 1, c + 1); CP_COMMIT(); CP_WAIT(1); }
        else           { CP_WAIT(0); }
        __syncthreads();

        uint32_t aB = uA + (uint32_t)st * A_STAGE;
        uint32_t bB = uB + (uint32_t)st * B_STAGE;
#pragma unroll
        for (int ks = 0; ks < 2; ks++) {
            uint32_t a[4][4];
#pragma unroll
            for (int am = 0; am < 4; am++) {
                int row = wm * 64 + am * 16 + (lane & 15);
                int col = ks * 16 + (lane >> 4) * 8;
                ldm_x4(a[am], aB + (uint32_t)(row * SROW_A + col) * 2);
            }
            int krow = ks * 16 + (lane & 15);
#pragma unroll
            for (int bn = 0; bn < 4; bn++) {
                int ncol = wn * 32 + bn * 8;
                uint32_t b[2];
                ldm_x2t(b, bB + (uint32_t)(krow * SROW_B + ncol) * 2);
#pragma unroll
                for (int am = 0; am < 4; am++)
                    mma16816(d[am][bn], a[am], b);
            }
        }
        __syncthreads();
    }

    int rbase = m0 + wm * 64 + (lane >> 2);
    int cbase = n0 + wn * 32 + (lane & 3) * 2;
#pragma unroll
    for (int am = 0; am < 4; am++) {
#pragma unroll
        for (int bn = 0; bn < 4; bn++) {
            int r = rbase + am * 16;
            int cc = cbase + bn * 8;
            float* dd = d[am][bn];
            *(float2*)(g_Y + (size_t)r * HID + cc)       = make_float2(dd[0], dd[1]);
            *(float2*)(g_Y + (size_t)(r + 8) * HID + cc) = make_float2(dd[2], dd[3]);
        }
    }
}

__global__ void k_combine(float* __restrict__ out) {
    int t = blockIdx.x;
    int r0 = g_tok_rows[t * 2], r1 = g_tok_rows[t * 2 + 1];
    float w0 = g_tok_w[t * 2], w1 = g_tok_w[t * 2 + 1];
    const float4* y0 = (const float4*)(g_Y + (size_t)r0 * HID);
    const float4* y1 = (const float4*)(g_Y + (size_t)r1 * HID);
    float4* o = (float4*)(out + (size_t)t * HID);
    for (int i = threadIdx.x; i < HID / 4; i += blockDim.x) {
        float4 a = y0[i], b = y1[i];
        float4 v;
        v.x = w0 * a.x + w1 * b.x;
        v.y = w0 * a.y + w1 * b.y;
        v.z = w0 * a.z + w1 * b.z;
        v.w = w0 * a.w + w1 * b.w;
        o[i] = v;
    }
}

// ---------- launch ----------
extern "C" void kernel_launch(void* const* d_in, const int* in_sizes, int n_in,
                              void* d_out, int out_size) {
    const float* hs   = (const float*)d_in[0];
    const float* gate = (const float*)d_in[1];
    const float* w1   = (const float*)d_in[2];
    const float* w3   = (const float*)d_in[3];
    const float* w2   = (const float*)d_in[4];
    float* out = (float*)d_out;

    __half *w1h, *w3h, *w2h;
    cudaGetSymbolAddress((void**)&w1h, g_w1h);
    cudaGetSymbolAddress((void**)&w3h, g_w3h);
    cudaGetSymbolAddress((void**)&w2h, g_w2h);

    cudaFuncSetAttribute(k_gemm13, cudaFuncAttributeMaxDynamicSharedMemorySize, SM13);
    cudaFuncSetAttribute(k_gemm2,  cudaFuncAttributeMaxDynamicSharedMemorySize, SM2);

    k_zero<<<1, 32>>>();
    k_router<<<T_TOK / 8, 256>>>(hs, gate, out);
    k_scan<<<1, 1>>>();
    k_assign<<<T_TOK / 256, 256>>>();
    k_gather<<<ROWS_MAX, 128>>>(hs);

    const int WN4 = NEXP * HID * INTER / 4;
    k_convert<<<4096, 256>>>(w1, w1h, WN4);
    k_convert<<<4096, 256>>>(w3, w3h, WN4);
    k_convert<<<4096, 256>>>(w2, w2h, WN4);

    k_gemm13<<<dim3(ROWS_MAX / 128, INTER / 128), 256, SM13>>>();
    k_gemm2 <<<dim3(ROWS_MAX / 128, HID / 128),   256, SM2 >>>();

    k_combine<<<T_TOK, 256>>>(out);
}

// round 6
// speedup vs baseline: 1.4822x; 1.0383x over previous
#include <cuda_runtime.h>
#include <cuda_fp16.h>
#include <cstdint>
#include <math.h>

constexpr int T_TOK = 4096;
constexpr int HID   = 2048;
constexpr int INTER = 5120;
constexpr int NEXP  = 8;
constexpr int ROWS_MAX = 9216;

// ---------- device scratch ----------
__device__ int   g_cnt[NEXP];
__device__ int   g_cursor[NEXP];
__device__ int   g_off[NEXP];
__device__ int   g_region[NEXP];
__device__ int   g_padded_total;
__device__ int   g_tok_e[T_TOK * 2];
__device__ float g_tok_w[T_TOK * 2];
__device__ int   g_tok_rows[T_TOK * 2];
__device__ int   g_row_token[ROWS_MAX];
__device__ __half g_Xg[(size_t)ROWS_MAX * HID];
__device__ __half g_G [(size_t)ROWS_MAX * INTER];
__device__ float  g_Y [(size_t)ROWS_MAX * HID];
__device__ __half g_w1h[(size_t)NEXP * HID * INTER];   // fp16, native [E][K=H][N=I]
__device__ __half g_w3h[(size_t)NEXP * HID * INTER];
__device__ __half g_w2h[(size_t)NEXP * INTER * HID];   // fp16, native [E][K=I][N=H]

// ---------- helpers ----------
__device__ __forceinline__ uint32_t smem_u32(const void* p) {
    uint32_t a;
    asm("{ .reg .u64 t; cvta.to.shared.u64 t, %1; cvt.u32.u64 %0, t; }" : "=r"(a) : "l"(p));
    return a;
}
__device__ __forceinline__ void cp16(uint32_t dst, const void* src) {
    asm volatile("cp.async.cg.shared.global [%0], [%1], 16;" :: "r"(dst), "l"(src));
}
#define CP_COMMIT() asm volatile("cp.async.commit_group;" ::: "memory")
#define CP_WAIT(n)  asm volatile("cp.async.wait_group %0;" :: "n"(n) : "memory")

__device__ __forceinline__ void ldm_x4(uint32_t* r, uint32_t a) {
    asm volatile("ldmatrix.sync.aligned.m8n8.x4.shared.b16 {%0,%1,%2,%3}, [%4];"
        : "=r"(r[0]), "=r"(r[1]), "=r"(r[2]), "=r"(r[3]) : "r"(a));
}
__device__ __forceinline__ void ldm_x2t(uint32_t* r, uint32_t a) {
    asm volatile("ldmatrix.sync.aligned.m8n8.x2.trans.shared.b16 {%0,%1}, [%2];"
        : "=r"(r[0]), "=r"(r[1]) : "r"(a));
}
__device__ __forceinline__ void mma16816(float* d, const uint32_t* a, const uint32_t* b) {
    asm volatile("mma.sync.aligned.m16n8k16.row.col.f32.f16.f16.f32 "
        "{%0,%1,%2,%3}, {%4,%5,%6,%7}, {%8,%9}, {%0,%1,%2,%3};"
        : "+f"(d[0]), "+f"(d[1]), "+f"(d[2]), "+f"(d[3])
        : "r"(a[0]), "r"(a[1]), "r"(a[2]), "r"(a[3]), "r"(b[0]), "r"(b[1]));
}
__device__ __forceinline__ float silu(float x) { return x / (1.f + expf(-x)); }

// ---------- small kernels ----------
__global__ void k_zero() {
    int t = threadIdx.x;
    if (t < NEXP) { g_cnt[t] = 0; g_cursor[t] = 0; }
}

__global__ void k_router(const float* __restrict__ hs, const float* __restrict__ gate,
                         float* __restrict__ out) {
    int warp = (blockIdx.x * blockDim.x + threadIdx.x) >> 5;
    int lane = threadIdx.x & 31;
    if (warp >= T_TOK) return;
    const float* x = hs + (size_t)warp * HID;
    float acc[NEXP];
#pragma unroll
    for (int e = 0; e < NEXP; e++) acc[e] = 0.f;
    for (int h = lane; h < HID; h += 32) {
        float xv = x[h];
        const float4* g4 = (const float4*)(gate + (size_t)h * NEXP);
        float4 a = g4[0], b = g4[1];
        acc[0] += xv * a.x; acc[1] += xv * a.y; acc[2] += xv * a.z; acc[3] += xv * a.w;
        acc[4] += xv * b.x; acc[5] += xv * b.y; acc[6] += xv * b.z; acc[7] += xv * b.w;
    }
#pragma unroll
    for (int e = 0; e < NEXP; e++)
#pragma unroll
        for (int o = 16; o; o >>= 1) acc[e] += __shfl_xor_sync(0xffffffffu, acc[e], o);
    if (lane == 0) {
        float* lo = out + (size_t)T_TOK * HID + (size_t)warp * NEXP;
#pragma unroll
        for (int e = 0; e < NEXP; e++) lo[e] = acc[e];
        int e0 = 0; float l0 = acc[0];
#pragma unroll
        for (int e = 1; e < NEXP; e++) if (acc[e] > l0) { l0 = acc[e]; e0 = e; }
        int e1 = -1; float l1 = -1e30f;
#pragma unroll
        for (int e = 0; e < NEXP; e++) if (e != e0 && acc[e] > l1) { l1 = acc[e]; e1 = e; }
        float p1 = expf(l1 - l0);
        float s = 1.f + p1;
        g_tok_e[warp * 2] = e0;      g_tok_e[warp * 2 + 1] = e1;
        g_tok_w[warp * 2] = 1.f / s; g_tok_w[warp * 2 + 1] = p1 / s;
        atomicAdd(&g_cnt[e0], 1);
        atomicAdd(&g_cnt[e1], 1);
    }
}

__global__ void k_scan() {
    int off = 0;
    for (int e = 0; e < NEXP; e++) {
        g_off[e] = off;
        int reg = ((g_cnt[e] + 127) / 128) * 128;
        g_region[e] = reg;
        off += reg;
    }
    g_padded_total = off;
}

__global__ void k_assign() {
    int t = blockIdx.x * blockDim.x + threadIdx.x;
    if (t >= T_TOK) return;
#pragma unroll
    for (int k = 0; k < 2; k++) {
        int e = g_tok_e[t * 2 + k];
        int pos = atomicAdd(&g_cursor[e], 1);
        int row = g_off[e] + pos;
        g_row_token[row] = t;
        g_tok_rows[t * 2 + k] = row;
    }
}

__global__ void k_gather(const float* __restrict__ hs) {
    int r = blockIdx.x;
    int e = 0;
    bool valid = (r < g_padded_total);
    if (valid) {
#pragma unroll
        for (int i = 0; i < NEXP; i++)
            if (r >= g_off[i] && r < g_off[i] + g_region[i]) e = i;
    }
    __half* dst = g_Xg + (size_t)r * HID;
    if (valid && (r - g_off[e]) < g_cnt[e]) {
        int t = g_row_token[r];
        const float4* src = (const float4*)(hs + (size_t)t * HID);
        __half2* d2 = (__half2*)dst;
        for (int i = threadIdx.x; i < HID / 4; i += blockDim.x) {
            float4 v = src[i];
            d2[2 * i]     = __floats2half2_rn(v.x, v.y);
            d2[2 * i + 1] = __floats2half2_rn(v.z, v.w);
        }
    } else {
        uint32_t* d = (uint32_t*)dst;
        for (int i = threadIdx.x; i < HID / 2; i += blockDim.x) d[i] = 0u;
    }
}

// straight fp32 -> fp16 convert, fully coalesced
__global__ void k_convert(const float* __restrict__ src, __half* __restrict__ dst, int n4) {
    int i = blockIdx.x * blockDim.x + threadIdx.x;
    int stride = gridDim.x * blockDim.x;
    const float4* s4 = (const float4*)src;
    __half2* d2 = (__half2*)dst;
    for (; i < n4; i += stride) {
        float4 v = s4[i];
        d2[2 * i]     = __floats2half2_rn(v.x, v.y);
        d2[2 * i + 1] = __floats2half2_rn(v.z, v.w);
    }
}

// ---------- GEMM kernels ----------
// 4-stage cp.async pipeline, one __syncthreads per K-chunk (32).
// A smem: [m=128][k=32] pitch 40 halves. B smem: [k=32][n=128] pitch 136 halves.
constexpr int STAGES  = 4;
constexpr int SROW_A  = 40;
constexpr int A_STAGE = 128 * SROW_A * 2;     // 10240 B
constexpr int SROW_B  = 136;
constexpr int B_STAGE = 32 * SROW_B * 2;      // 8704 B
constexpr int OFF_B1  = STAGES * A_STAGE;                 // 40960
constexpr int OFF_B3  = OFF_B1 + STAGES * B_STAGE;        // 75776
constexpr int SM13    = OFF_B3 + STAGES * B_STAGE;        // 110592
constexpr int SM2     = OFF_B1 + STAGES * B_STAGE;        // 75776

// Fused GEMM1: G = silu(X @ W1) * (X @ W3). K=HID.
__global__ void __launch_bounds__(256, 1) k_gemm13() {
    extern __shared__ char sm[];
    int m0 = blockIdx.x * 128;
    if (m0 >= g_padded_total) return;
    int e = 0;
#pragma unroll
    for (int i = 0; i < NEXP; i++)
        if (m0 >= g_off[i] && m0 < g_off[i] + g_region[i]) e = i;
    int n0 = blockIdx.y * 128;

    const __half* Ag  = g_Xg + (size_t)m0 * HID;
    const __half* B1g = g_w1h + (size_t)e * HID * INTER + n0;
    const __half* B3g = g_w3h + (size_t)e * HID * INTER + n0;

    int tid = threadIdx.x;
    int wid = tid >> 5, lane = tid & 31;
    int wm = wid >> 2, wn = wid & 3;

    uint32_t uA  = smem_u32(sm);
    uint32_t uB1 = uA + OFF_B1;
    uint32_t uB3 = uA + OFF_B3;

    int ra0 = tid >> 2,          qa0 = tid & 3;
    int ra1 = (tid + 256) >> 2,  qa1 = tid & 3;
    int rb0 = tid >> 4,          qb0 = tid & 15;
    int rb1 = (tid + 256) >> 4,  qb1 = tid & 15;

    float d1[4][4][4], d3[4][4][4];
#pragma unroll
    for (int i = 0; i < 4; i++)
#pragma unroll
        for (int j = 0; j < 4; j++)
#pragma unroll
            for (int k = 0; k < 4; k++) { d1[i][j][k] = 0.f; d3[i][j][k] = 0.f; }

    const int NC = HID / 32;   // 64

    auto load_chunk = [&](int st, int c) {
        int kg = c * 32;
        uint32_t ao = uA + (uint32_t)st * A_STAGE;
        cp16(ao + (uint32_t)(ra0 * SROW_A + qa0 * 8) * 2, Ag + (size_t)ra0 * HID + kg + qa0 * 8);
        cp16(ao + (uint32_t)(ra1 * SROW_A + qa1 * 8) * 2, Ag + (size_t)ra1 * HID + kg + qa1 * 8);
        uint32_t b1o = uB1 + (uint32_t)st * B_STAGE;
        uint32_t b3o = uB3 + (uint32_t)st * B_STAGE;
        cp16(b1o + (uint32_t)(rb0 * SROW_B + qb0 * 8) * 2, B1g + (size_t)(kg + rb0) * INTER + qb0 * 8);
        cp16(b1o + (uint32_t)(rb1 * SROW_B + qb1 * 8) * 2, B1g + (size_t)(kg + rb1) * INTER + qb1 * 8);
        cp16(b3o + (uint32_t)(rb0 * SROW_B + qb0 * 8) * 2, B3g + (size_t)(kg + rb0) * INTER + qb0 * 8);
        cp16(b3o + (uint32_t)(rb1 * SROW_B + qb1 * 8) * 2, B3g + (size_t)(kg + rb1) * INTER + qb1 * 8);
    };

    // prologue: fill STAGES-1 stages
#pragma unroll
    for (int p = 0; p < STAGES - 1; p++) { load_chunk(p, p); CP_COMMIT(); }

    for (int c = 0; c < NC; c++) {
        int st = c & (STAGES - 1);
        CP_WAIT(STAGES - 2);       // stage c complete
        __syncthreads();           // all warps done with stage being refilled
        if (c + STAGES - 1 < NC) load_chunk((c + STAGES - 1) & (STAGES - 1), c + STAGES - 1);
        CP_COMMIT();

        uint32_t aB  = uA  + (uint32_t)st * A_STAGE;
        uint32_t b1B = uB1 + (uint32_t)st * B_STAGE;
        uint32_t b3B = uB3 + (uint32_t)st * B_STAGE;
#pragma unroll
        for (int ks = 0; ks < 2; ks++) {
            uint32_t a[4][4];
#pragma unroll
            for (int am = 0; am < 4; am++) {
                int row = wm * 64 + am * 16 + (lane & 15);
                int col = ks * 16 + (lane >> 4) * 8;
                ldm_x4(a[am], aB + (uint32_t)(row * SROW_A + col) * 2);
            }
            int krow = ks * 16 + (lane & 15);
#pragma unroll
            for (int bn = 0; bn < 4; bn++) {
                int ncol = wn * 32 + bn * 8;
                uint32_t off = (uint32_t)(krow * SROW_B + ncol) * 2;
                uint32_t b1[2], b3[2];
                ldm_x2t(b1, b1B + off);
                ldm_x2t(b3, b3B + off);
#pragma unroll
                for (int am = 0; am < 4; am++) {
                    mma16816(d1[am][bn], a[am], b1);
                    mma16816(d3[am][bn], a[am], b3);
                }
            }
        }
    }

    int rbase = m0 + wm * 64 + (lane >> 2);
    int cbase = n0 + wn * 32 + (lane & 3) * 2;
#pragma unroll
    for (int am = 0; am < 4; am++) {
#pragma unroll
        for (int bn = 0; bn < 4; bn++) {
            int r = rbase + am * 16;
            int cc = cbase + bn * 8;
            float* a1 = d1[am][bn];
            float* a3 = d3[am][bn];
            float g0 = silu(a1[0]) * a3[0];
            float g1 = silu(a1[1]) * a3[1];
            float g2 = silu(a1[2]) * a3[2];
            float g3 = silu(a1[3]) * a3[3];
            *(__half2*)(g_G + (size_t)r * INTER + cc)       = __floats2half2_rn(g0, g1);
            *(__half2*)(g_G + (size_t)(r + 8) * INTER + cc) = __floats2half2_rn(g2, g3);
        }
    }
}

// GEMM2: Y = G @ W2, fp32 out. K=INTER.
__global__ void __launch_bounds__(256, 1) k_gemm2() {
    extern __shared__ char sm[];
    int m0 = blockIdx.x * 128;
    if (m0 >= g_padded_total) return;
    int e = 0;
#pragma unroll
    for (int i = 0; i < NEXP; i++)
        if (m0 >= g_off[i] && m0 < g_off[i] + g_region[i]) e = i;
    int n0 = blockIdx.y * 128;

    const __half* Ag = g_G + (size_t)m0 * INTER;
    const __half* Bg = g_w2h + (size_t)e * INTER * HID + n0;

    int tid = threadIdx.x;
    int wid = tid >> 5, lane = tid & 31;
    int wm = wid >> 2, wn = wid & 3;

    uint32_t uA = smem_u32(sm);
    uint32_t uB = uA + OFF_B1;

    int ra0 = tid >> 2,          qa0 = tid & 3;
    int ra1 = (tid + 256) >> 2,  qa1 = tid & 3;
    int rb0 = tid >> 4,          qb0 = tid & 15;
    int rb1 = (tid + 256) >> 4,  qb1 = tid & 15;

    float d[4][4][4];
#pragma unroll
    for (int i = 0; i < 4; i++)
#pragma unroll
        for (int j = 0; j < 4; j++)
#pragma unroll
            for (int k = 0; k < 4; k++) d[i][j][k] = 0.f;

    const int NC = INTER / 32;  // 160

    auto load_chunk = [&](int st, int c) {
        int kg = c * 32;
        uint32_t ao = uA + (uint32_t)st * A_STAGE;
        cp16(ao + (uint32_t)(ra0 * SROW_A + qa0 * 8) * 2, Ag + (size_t)ra0 * INTER + kg + qa0 * 8);
        cp16(ao + (uint32_t)(ra1 * SROW_A + qa1 * 8) * 2, Ag + (size_t)ra1 * INTER + kg + qa1 * 8);
        uint32_t bo = uB + (uint32_t)st * B_STAGE;
        cp16(bo + (uint32_t)(rb0 * SROW_B + qb0 * 8) * 2, Bg + (size_t)(kg + rb0) * HID + qb0 * 8);
        cp16(bo + (uint32_t)(rb1 * SROW_B + qb1 * 8) * 2, Bg + (size_t)(kg + rb1) * HID + qb1 * 8);
    };

#pragma unroll
    for (int p = 0; p < STAGES - 1; p++) { load_chunk(p, p); CP_COMMIT(); }

    for (int c = 0; c < NC; c++) {
        int st = c & (STAGES - 1);
        CP_WAIT(STAGES - 2);
        __syncthreads();
        if (c + STAGES - 1 < NC) load_chunk((c + STAGES - 1) & (STAGES - 1), c + STAGES - 1);
        CP_COMMIT();

        uint32_t aB = uA + (uint32_t)st * A_STAGE;
        uint32_t bB = uB + (uint32_t)st * B_STAGE;
#pragma unroll
        for (int ks = 0; ks < 2; ks++) {
            uint32_t a[4][4];
#pragma unroll
            for (int am = 0; am < 4; am++) {
                int row = wm * 64 + am * 16 + (lane & 15);
                int col = ks * 16 + (lane >> 4) * 8;
                ldm_x4(a[am], aB + (uint32_t)(row * SROW_A + col) * 2);
            }
            int krow = ks * 16 + (lane & 15);
#pragma unroll
            for (int bn = 0; bn < 4; bn++) {
                int ncol = wn * 32 + bn * 8;
                uint32_t b[2];
                ldm_x2t(b, bB + (uint32_t)(krow * SROW_B + ncol) * 2);
#pragma unroll
                for (int am = 0; am < 4; am++)
                    mma16816(d[am][bn], a[am], b);
            }
        }
    }

    int rbase = m0 + wm * 64 + (lane >> 2);
    int cbase = n0 + wn * 32 + (lane & 3) * 2;
#pragma unroll
    for (int am = 0; am < 4; am++) {
#pragma unroll
        for (int bn = 0; bn < 4; bn++) {
            int r = rbase + am * 16;
            int cc = cbase + bn * 8;
            float* dd = d[am][bn];
            *(float2*)(g_Y + (size_t)r * HID + cc)       = make_float2(dd[0], dd[1]);
            *(float2*)(g_Y + (size_t)(r + 8) * HID + cc) = make_float2(dd[2], dd[3]);
        }
    }
}

__global__ void k_combine(float* __restrict__ out) {
    int t = blockIdx.x;
    int r0 = g_tok_rows[t * 2], r1 = g_tok_rows[t * 2 + 1];
    float w0 = g_tok_w[t * 2], w1 = g_tok_w[t * 2 + 1];
    const float4* y0 = (const float4*)(g_Y + (size_t)r0 * HID);
    const float4* y1 = (const float4*)(g_Y + (size_t)r1 * HID);
    float4* o = (float4*)(out + (size_t)t * HID);
    for (int i = threadIdx.x; i < HID / 4; i += blockDim.x) {
        float4 a = y0[i], b = y1[i];
        float4 v;
        v.x = w0 * a.x + w1 * b.x;
        v.y = w0 * a.y + w1 * b.y;
        v.z = w0 * a.z + w1 * b.z;
        v.w = w0 * a.w + w1 * b.w;
        o[i] = v;
    }
}

// ---------- launch ----------
extern "C" void kernel_launch(void* const* d_in, const int* in_sizes, int n_in,
                              void* d_out, int out_size) {
    const float* hs   = (const float*)d_in[0];
    const float* gate = (const float*)d_in[1];
    const float* w1   = (const float*)d_in[2];
    const float* w3   = (const float*)d_in[3];
    const float* w2   = (const float*)d_in[4];
    float* out = (float*)d_out;

    __half *w1h, *w3h, *w2h;
    cudaGetSymbolAddress((void**)&w1h, g_w1h);
    cudaGetSymbolAddress((void**)&w3h, g_w3h);
    cudaGetSymbolAddress((void**)&w2h, g_w2h);

    cudaFuncSetAttribute(k_gemm13, cudaFuncAttributeMaxDynamicSharedMemorySize, SM13);
    cudaFuncSetAttribute(k_gemm2,  cudaFuncAttributeMaxDynamicSharedMemorySize, SM2);

    k_zero<<<1, 32>>>();
    k_router<<<T_TOK / 8, 256>>>(hs, gate, out);
    k_scan<<<1, 1>>>();
    k_assign<<<T_TOK / 256, 256>>>();
    k_gather<<<ROWS_MAX, 128>>>(hs);

    const int WN4 = NEXP * HID * INTER / 4;
    k_convert<<<4096, 256>>>(w1, w1h, WN4);
    k_convert<<<4096, 256>>>(w3, w3h, WN4);
    k_convert<<<4096, 256>>>(w2, w2h, WN4);

    k_gemm13<<<dim3(ROWS_MAX / 128, INTER / 128), 256, SM13>>>();
    k_gemm2 <<<dim3(ROWS_MAX / 128, HID / 128),   256, SM2 >>>();

    k_combine<<<T_TOK, 256>>>(out);
}

// round 7
// speedup vs baseline: 1.5584x; 1.0514x over previous
#include <cuda_runtime.h>
#include <cuda_fp16.h>
#include <cstdint>
#include <math.h>

constexpr int T_TOK = 4096;
constexpr int HID   = 2048;
constexpr int INTER = 5120;
constexpr int NEXP  = 8;
constexpr int ROWS_MAX = 9216;

// ---------- device scratch ----------
__device__ int   g_cnt[NEXP];
__device__ int   g_cursor[NEXP];
__device__ int   g_off[NEXP];
__device__ int   g_region[NEXP];
__device__ int   g_padded_total;
__device__ int   g_tok_e[T_TOK * 2];
__device__ float g_tok_w[T_TOK * 2];
__device__ int   g_tok_rows[T_TOK * 2];
__device__ int   g_row_token[ROWS_MAX];
__device__ __half g_Xg[(size_t)ROWS_MAX * HID];
__device__ __half g_G [(size_t)ROWS_MAX * INTER];
__device__ float  g_Y [(size_t)ROWS_MAX * HID];
__device__ __half g_w1h[(size_t)NEXP * HID * INTER];   // fp16, native [E][K=H][N=I]
__device__ __half g_w3h[(size_t)NEXP * HID * INTER];
__device__ __half g_w2h[(size_t)NEXP * INTER * HID];   // fp16, native [E][K=I][N=H]

// ---------- helpers ----------
__device__ __forceinline__ uint32_t smem_u32(const void* p) {
    uint32_t a;
    asm("{ .reg .u64 t; cvta.to.shared.u64 t, %1; cvt.u32.u64 %0, t; }" : "=r"(a) : "l"(p));
    return a;
}
__device__ __forceinline__ void cp16(uint32_t dst, const void* src) {
    asm volatile("cp.async.cg.shared.global [%0], [%1], 16;" :: "r"(dst), "l"(src));
}
#define CP_COMMIT() asm volatile("cp.async.commit_group;" ::: "memory")
#define CP_WAIT(n)  asm volatile("cp.async.wait_group %0;" :: "n"(n) : "memory")

__device__ __forceinline__ void ldm_x4(uint32_t* r, uint32_t a) {
    asm volatile("ldmatrix.sync.aligned.m8n8.x4.shared.b16 {%0,%1,%2,%3}, [%4];"
        : "=r"(r[0]), "=r"(r[1]), "=r"(r[2]), "=r"(r[3]) : "r"(a));
}
__device__ __forceinline__ void ldm_x4t(uint32_t* r, uint32_t a) {
    asm volatile("ldmatrix.sync.aligned.m8n8.x4.trans.shared.b16 {%0,%1,%2,%3}, [%4];"
        : "=r"(r[0]), "=r"(r[1]), "=r"(r[2]), "=r"(r[3]) : "r"(a));
}
__device__ __forceinline__ void mma16816(float* d, const uint32_t* a, const uint32_t* b) {
    asm volatile("mma.sync.aligned.m16n8k16.row.col.f32.f16.f16.f32 "
        "{%0,%1,%2,%3}, {%4,%5,%6,%7}, {%8,%9}, {%0,%1,%2,%3};"
        : "+f"(d[0]), "+f"(d[1]), "+f"(d[2]), "+f"(d[3])
        : "r"(a[0]), "r"(a[1]), "r"(a[2]), "r"(a[3]), "r"(b[0]), "r"(b[1]));
}
__device__ __forceinline__ float silu(float x) { return x / (1.f + expf(-x)); }

// ---------- small kernels ----------
__global__ void k_zero() {
    int t = threadIdx.x;
    if (t < NEXP) { g_cnt[t] = 0; g_cursor[t] = 0; }
}

__global__ void k_router(const float* __restrict__ hs, const float* __restrict__ gate,
                         float* __restrict__ out) {
    int warp = (blockIdx.x * blockDim.x + threadIdx.x) >> 5;
    int lane = threadIdx.x & 31;
    if (warp >= T_TOK) return;
    const float* x = hs + (size_t)warp * HID;
    float acc[NEXP];
#pragma unroll
    for (int e = 0; e < NEXP; e++) acc[e] = 0.f;
    for (int h = lane; h < HID; h += 32) {
        float xv = x[h];
        const float4* g4 = (const float4*)(gate + (size_t)h * NEXP);
        float4 a = g4[0], b = g4[1];
        acc[0] += xv * a.x; acc[1] += xv * a.y; acc[2] += xv * a.z; acc[3] += xv * a.w;
        acc[4] += xv * b.x; acc[5] += xv * b.y; acc[6] += xv * b.z; acc[7] += xv * b.w;
    }
#pragma unroll
    for (int e = 0; e < NEXP; e++)
#pragma unroll
        for (int o = 16; o; o >>= 1) acc[e] += __shfl_xor_sync(0xffffffffu, acc[e], o);
    if (lane == 0) {
        float* lo = out + (size_t)T_TOK * HID + (size_t)warp * NEXP;
#pragma unroll
        for (int e = 0; e < NEXP; e++) lo[e] = acc[e];
        int e0 = 0; float l0 = acc[0];
#pragma unroll
        for (int e = 1; e < NEXP; e++) if (acc[e] > l0) { l0 = acc[e]; e0 = e; }
        int e1 = -1; float l1 = -1e30f;
#pragma unroll
        for (int e = 0; e < NEXP; e++) if (e != e0 && acc[e] > l1) { l1 = acc[e]; e1 = e; }
        float p1 = expf(l1 - l0);
        float s = 1.f + p1;
        g_tok_e[warp * 2] = e0;      g_tok_e[warp * 2 + 1] = e1;
        g_tok_w[warp * 2] = 1.f / s; g_tok_w[warp * 2 + 1] = p1 / s;
        atomicAdd(&g_cnt[e0], 1);
        atomicAdd(&g_cnt[e1], 1);
    }
}

__global__ void k_scan() {
    int off = 0;
    for (int e = 0; e < NEXP; e++) {
        g_off[e] = off;
        int reg = ((g_cnt[e] + 127) / 128) * 128;
        g_region[e] = reg;
        off += reg;
    }
    g_padded_total = off;
}

__global__ void k_assign() {
    int t = blockIdx.x * blockDim.x + threadIdx.x;
    if (t >= T_TOK) return;
#pragma unroll
    for (int k = 0; k < 2; k++) {
        int e = g_tok_e[t * 2 + k];
        int pos = atomicAdd(&g_cursor[e], 1);
        int row = g_off[e] + pos;
        g_row_token[row] = t;
        g_tok_rows[t * 2 + k] = row;
    }
}

__global__ void k_gather(const float* __restrict__ hs) {
    int r = blockIdx.x;
    int e = 0;
    bool valid = (r < g_padded_total);
    if (valid) {
#pragma unroll
        for (int i = 0; i < NEXP; i++)
            if (r >= g_off[i] && r < g_off[i] + g_region[i]) e = i;
    }
    __half* dst = g_Xg + (size_t)r * HID;
    if (valid && (r - g_off[e]) < g_cnt[e]) {
        int t = g_row_token[r];
        const float4* src = (const float4*)(hs + (size_t)t * HID);
        __half2* d2 = (__half2*)dst;
        for (int i = threadIdx.x; i < HID / 4; i += blockDim.x) {
            float4 v = src[i];
            d2[2 * i]     = __floats2half2_rn(v.x, v.y);
            d2[2 * i + 1] = __floats2half2_rn(v.z, v.w);
        }
    } else {
        uint32_t* d = (uint32_t*)dst;
        for (int i = threadIdx.x; i < HID / 2; i += blockDim.x) d[i] = 0u;
    }
}

// straight fp32 -> fp16 convert, fully coalesced
__global__ void k_convert(const float* __restrict__ src, __half* __restrict__ dst, int n4) {
    int i = blockIdx.x * blockDim.x + threadIdx.x;
    int stride = gridDim.x * blockDim.x;
    const float4* s4 = (const float4*)src;
    __half2* d2 = (__half2*)dst;
    for (; i < n4; i += stride) {
        float4 v = s4[i];
        d2[2 * i]     = __floats2half2_rn(v.x, v.y);
        d2[2 * i + 1] = __floats2half2_rn(v.z, v.w);
    }
}

// ---------- GEMM kernels ----------
constexpr int STAGES  = 4;
constexpr int SROW_A  = 40;
constexpr int A_STAGE = 128 * SROW_A * 2;     // 10240 B
constexpr int SROW_B  = 136;
constexpr int B_STAGE = 32 * SROW_B * 2;      // 8704 B
constexpr int OFF_B1  = STAGES * A_STAGE;                 // 40960
constexpr int OFF_B3  = OFF_B1 + STAGES * B_STAGE;        // 75776
constexpr int SM13    = OFF_B3 + STAGES * B_STAGE;        // 110592
constexpr int SM2     = OFF_B1 + STAGES * B_STAGE;        // 75776

// Fused GEMM1: G = silu(X @ W1) * (X @ W3). K=HID.
__global__ void __launch_bounds__(256, 1) k_gemm13() {
    extern __shared__ char sm[];
    int m0 = blockIdx.x * 128;
    if (m0 >= g_padded_total) return;
    int e = 0;
#pragma unroll
    for (int i = 0; i < NEXP; i++)
        if (m0 >= g_off[i] && m0 < g_off[i] + g_region[i]) e = i;
    int n0 = blockIdx.y * 128;

    const __half* Ag  = g_Xg + (size_t)m0 * HID;
    const __half* B1g = g_w1h + (size_t)e * HID * INTER + n0;
    const __half* B3g = g_w3h + (size_t)e * HID * INTER + n0;

    int tid = threadIdx.x;
    int wid = tid >> 5, lane = tid & 31;
    int wm = wid >> 2, wn = wid & 3;

    uint32_t uA  = smem_u32(sm);
    uint32_t uB1 = uA + OFF_B1;
    uint32_t uB3 = uA + OFF_B3;

    int ra0 = tid >> 2,          qa0 = tid & 3;
    int ra1 = (tid + 256) >> 2,  qa1 = tid & 3;
    int rb0 = tid >> 4,          qb0 = tid & 15;
    int rb1 = (tid + 256) >> 4,  qb1 = tid & 15;

    float d1[4][4][4], d3[4][4][4];
#pragma unroll
    for (int i = 0; i < 4; i++)
#pragma unroll
        for (int j = 0; j < 4; j++)
#pragma unroll
            for (int k = 0; k < 4; k++) { d1[i][j][k] = 0.f; d3[i][j][k] = 0.f; }

    const int NC = HID / 32;   // 64

    auto load_chunk = [&](int st, int c) {
        int kg = c * 32;
        uint32_t ao = uA + (uint32_t)st * A_STAGE;
        cp16(ao + (uint32_t)(ra0 * SROW_A + qa0 * 8) * 2, Ag + (size_t)ra0 * HID + kg + qa0 * 8);
        cp16(ao + (uint32_t)(ra1 * SROW_A + qa1 * 8) * 2, Ag + (size_t)ra1 * HID + kg + qa1 * 8);
        uint32_t b1o = uB1 + (uint32_t)st * B_STAGE;
        uint32_t b3o = uB3 + (uint32_t)st * B_STAGE;
        cp16(b1o + (uint32_t)(rb0 * SROW_B + qb0 * 8) * 2, B1g + (size_t)(kg + rb0) * INTER + qb0 * 8);
        cp16(b1o + (uint32_t)(rb1 * SROW_B + qb1 * 8) * 2, B1g + (size_t)(kg + rb1) * INTER + qb1 * 8);
        cp16(b3o + (uint32_t)(rb0 * SROW_B + qb0 * 8) * 2, B3g + (size_t)(kg + rb0) * INTER + qb0 * 8);
        cp16(b3o + (uint32_t)(rb1 * SROW_B + qb1 * 8) * 2, B3g + (size_t)(kg + rb1) * INTER + qb1 * 8);
    };

#pragma unroll
    for (int p = 0; p < STAGES - 1; p++) { load_chunk(p, p); CP_COMMIT(); }

    int bcol = (lane >> 4) * 8;          // x4t column sub-offset
    for (int c = 0; c < NC; c++) {
        int st = c & (STAGES - 1);
        CP_WAIT(STAGES - 2);
        __syncthreads();
        if (c + STAGES - 1 < NC) load_chunk((c + STAGES - 1) & (STAGES - 1), c + STAGES - 1);
        CP_COMMIT();

        uint32_t aB  = uA  + (uint32_t)st * A_STAGE;
        uint32_t b1B = uB1 + (uint32_t)st * B_STAGE;
        uint32_t b3B = uB3 + (uint32_t)st * B_STAGE;
#pragma unroll
        for (int ks = 0; ks < 2; ks++) {
            uint32_t a[4][4];
#pragma unroll
            for (int am = 0; am < 4; am++) {
                int row = wm * 64 + am * 16 + (lane & 15);
                int col = ks * 16 + (lane >> 4) * 8;
                ldm_x4(a[am], aB + (uint32_t)(row * SROW_A + col) * 2);
            }
            int krow = ks * 16 + (lane & 15);
#pragma unroll
            for (int bnp = 0; bnp < 2; bnp++) {        // 16 cols per x4t
                int ncol = wn * 32 + bnp * 16 + bcol;
                uint32_t off = (uint32_t)(krow * SROW_B + ncol) * 2;
                uint32_t b1[4], b3[4];
                ldm_x4t(b1, b1B + off);
                ldm_x4t(b3, b3B + off);
#pragma unroll
                for (int am = 0; am < 4; am++) {
                    mma16816(d1[am][2 * bnp],     a[am], b1);
                    mma16816(d1[am][2 * bnp + 1], a[am], b1 + 2);
                    mma16816(d3[am][2 * bnp],     a[am], b3);
                    mma16816(d3[am][2 * bnp + 1], a[am], b3 + 2);
                }
            }
        }
    }

    int rbase = m0 + wm * 64 + (lane >> 2);
    int cbase = n0 + wn * 32 + (lane & 3) * 2;
#pragma unroll
    for (int am = 0; am < 4; am++) {
#pragma unroll
        for (int bn = 0; bn < 4; bn++) {
            int r = rbase + am * 16;
            int cc = cbase + bn * 8;
            float* a1 = d1[am][bn];
            float* a3 = d3[am][bn];
            float g0 = silu(a1[0]) * a3[0];
            float g1 = silu(a1[1]) * a3[1];
            float g2 = silu(a1[2]) * a3[2];
            float g3 = silu(a1[3]) * a3[3];
            *(__half2*)(g_G + (size_t)r * INTER + cc)       = __floats2half2_rn(g0, g1);
            *(__half2*)(g_G + (size_t)(r + 8) * INTER + cc) = __floats2half2_rn(g2, g3);
        }
    }
}

// GEMM2: Y = G @ W2, fp32 out. K=INTER.
__global__ void __launch_bounds__(256, 1) k_gemm2() {
    extern __shared__ char sm[];
    int m0 = blockIdx.x * 128;
    if (m0 >= g_padded_total) return;
    int e = 0;
#pragma unroll
    for (int i = 0; i < NEXP; i++)
        if (m0 >= g_off[i] && m0 < g_off[i] + g_region[i]) e = i;
    int n0 = blockIdx.y * 128;

    const __half* Ag = g_G + (size_t)m0 * INTER;
    const __half* Bg = g_w2h + (size_t)e * INTER * HID + n0;

    int tid = threadIdx.x;
    int wid = tid >> 5, lane = tid & 31;
    int wm = wid >> 2, wn = wid & 3;

    uint32_t uA = smem_u32(sm);
    uint32_t uB = uA + OFF_B1;

    int ra0 = tid >> 2,          qa0 = tid & 3;
    int ra1 = (tid + 256) >> 2,  qa1 = tid & 3;
    int rb0 = tid >> 4,          qb0 = tid & 15;
    int rb1 = (tid + 256) >> 4,  qb1 = tid & 15;

    float d[4][4][4];
#pragma unroll
    for (int i = 0; i < 4; i++)
#pragma unroll
        for (int j = 0; j < 4; j++)
#pragma unroll
            for (int k = 0; k < 4; k++) d[i][j][k] = 0.f;

    const int NC = INTER / 32;  // 160

    auto load_chunk = [&](int st, int c) {
        int kg = c * 32;
        uint32_t ao = uA + (uint32_t)st * A_STAGE;
        cp16(ao + (uint32_t)(ra0 * SROW_A + qa0 * 8) * 2, Ag + (size_t)ra0 * INTER + kg + qa0 * 8);
        cp16(ao + (uint32_t)(ra1 * SROW_A + qa1 * 8) * 2, Ag + (size_t)ra1 * INTER + kg + qa1 * 8);
        uint32_t bo = uB + (uint32_t)st * B_STAGE;
        cp16(bo + (uint32_t)(rb0 * SROW_B + qb0 * 8) * 2, Bg + (size_t)(kg + rb0) * HID + qb0 * 8);
        cp16(bo + (uint32_t)(rb1 * SROW_B + qb1 * 8) * 2, Bg + (size_t)(kg + rb1) * HID + qb1 * 8);
    };

#pragma unroll
    for (int p = 0; p < STAGES - 1; p++) { load_chunk(p, p); CP_COMMIT(); }

    int bcol = (lane >> 4) * 8;
    for (int c = 0; c < NC; c++) {
        int st = c & (STAGES - 1);
        CP_WAIT(STAGES - 2);
        __syncthreads();
        if (c + STAGES - 1 < NC) load_chunk((c + STAGES - 1) & (STAGES - 1), c + STAGES - 1);
        CP_COMMIT();

        uint32_t aB = uA + (uint32_t)st * A_STAGE;
        uint32_t bB = uB + (uint32_t)st * B_STAGE;
#pragma unroll
        for (int ks = 0; ks < 2; ks++) {
            uint32_t a[4][4];
#pragma unroll
            for (int am = 0; am < 4; am++) {
                int row = wm * 64 + am * 16 + (lane & 15);
                int col = ks * 16 + (lane >> 4) * 8;
                ldm_x4(a[am], aB + (uint32_t)(row * SROW_A + col) * 2);
            }
            int krow = ks * 16 + (lane & 15);
#pragma unroll
            for (int bnp = 0; bnp < 2; bnp++) {
                int ncol = wn * 32 + bnp * 16 + bcol;
                uint32_t b[4];
                ldm_x4t(b, bB + (uint32_t)(krow * SROW_B + ncol) * 2);
#pragma unroll
                for (int am = 0; am < 4; am++) {
                    mma16816(d[am][2 * bnp],     a[am], b);
                    mma16816(d[am][2 * bnp + 1], a[am], b + 2);
                }
            }
        }
    }

    int rbase = m0 + wm * 64 + (lane >> 2);
    int cbase = n0 + wn * 32 + (lane & 3) * 2;
#pragma unroll
    for (int am = 0; am < 4; am++) {
#pragma unroll
        for (int bn = 0; bn < 4; bn++) {
            int r = rbase + am * 16;
            int cc = cbase + bn * 8;
            float* dd = d[am][bn];
            *(float2*)(g_Y + (size_t)r * HID + cc)       = make_float2(dd[0], dd[1]);
            *(float2*)(g_Y + (size_t)(r + 8) * HID + cc) = make_float2(dd[2], dd[3]);
        }
    }
}

__global__ void k_combine(float* __restrict__ out) {
    int t = blockIdx.x;
    int r0 = g_tok_rows[t * 2], r1 = g_tok_rows[t * 2 + 1];
    float w0 = g_tok_w[t * 2], w1 = g_tok_w[t * 2 + 1];
    const float4* y0 = (const float4*)(g_Y + (size_t)r0 * HID);
    const float4* y1 = (const float4*)(g_Y + (size_t)r1 * HID);
    float4* o = (float4*)(out + (size_t)t * HID);
    for (int i = threadIdx.x; i < HID / 4; i += blockDim.x) {
        float4 a = y0[i], b = y1[i];
        float4 v;
        v.x = w0 * a.x + w1 * b.x;
        v.y = w0 * a.y + w1 * b.y;
        v.z = w0 * a.z + w1 * b.z;
        v.w = w0 * a.w + w1 * b.w;
        o[i] = v;
    }
}

// ---------- launch ----------
extern "C" void kernel_launch(void* const* d_in, const int* in_sizes, int n_in,
                              void* d_out, int out_size) {
    const float* hs   = (const float*)d_in[0];
    const float* gate = (const float*)d_in[1];
    const float* w1   = (const float*)d_in[2];
    const float* w3   = (const float*)d_in[3];
    const float* w2   = (const float*)d_in[4];
    float* out = (float*)d_out;

    __half *w1h, *w3h, *w2h;
    cudaGetSymbolAddress((void**)&w1h, g_w1h);
    cudaGetSymbolAddress((void**)&w3h, g_w3h);
    cudaGetSymbolAddress((void**)&w2h, g_w2h);

    static cudaStream_t s1 = nullptr, s2 = nullptr;
    static cudaEvent_t evF = nullptr, evR = nullptr, evW2 = nullptr;
    if (!s1) {
        cudaStreamCreateWithFlags(&s1, cudaStreamNonBlocking);
        cudaStreamCreateWithFlags(&s2, cudaStreamNonBlocking);
        cudaEventCreateWithFlags(&evF,  cudaEventDisableTiming);
        cudaEventCreateWithFlags(&evR,  cudaEventDisableTiming);
        cudaEventCreateWithFlags(&evW2, cudaEventDisableTiming);
        cudaFuncSetAttribute(k_gemm13, cudaFuncAttributeMaxDynamicSharedMemorySize, SM13);
        cudaFuncSetAttribute(k_gemm2,  cudaFuncAttributeMaxDynamicSharedMemorySize, SM2);
    }

    const int WN4 = NEXP * HID * INTER / 4;

    // fork
    cudaEventRecord(evF, 0);
    cudaStreamWaitEvent(s1, evF, 0);
    cudaStreamWaitEvent(s2, evF, 0);

    // s1: routing chain + gather
    k_zero<<<1, 32, 0, s1>>>();
    k_router<<<T_TOK / 8, 256, 0, s1>>>(hs, gate, out);
    k_scan<<<1, 1, 0, s1>>>();
    k_assign<<<T_TOK / 256, 256, 0, s1>>>();
    k_gather<<<ROWS_MAX, 128, 0, s1>>>(hs);
    cudaEventRecord(evR, s1);

    // s2: w2 convert (only needed by gemm2)
    k_convert<<<4096, 256, 0, s2>>>(w2, w2h, WN4);
    cudaEventRecord(evW2, s2);

    // main: w1/w3 converts, then join
    k_convert<<<4096, 256>>>(w1, w1h, WN4);
    k_convert<<<4096, 256>>>(w3, w3h, WN4);
    cudaStreamWaitEvent(0, evR, 0);

    k_gemm13<<<dim3(ROWS_MAX / 128, INTER / 128), 256, SM13>>>();
    cudaStreamWaitEvent(0, evW2, 0);
    k_gemm2 <<<dim3(ROWS_MAX / 128, HID / 128),   256, SM2 >>>();

    k_combine<<<T_TOK, 256>>>(out);
}